// round 1
// baseline (speedup 1.0000x reference)
#include <cuda_runtime.h>
#include <cuda_bf16.h>
#include <math.h>

// Problem constants
#define NS 1024          // speakers
#define MU 20            // utterances per speaker
#define DD 256           // embedding dim
#define RR (NS*MU)       // total rows = 20480

// Scratch (device globals: allocation-free requirement)
__device__ float g_uhat[RR * DD];     // normalized utterances   21 MB
__device__ float g_chat[NS * DD];     // normalized centroids     1 MB
__device__ float g_cself[RR];         // self (leave-one-out) cosine
__device__ float g_cs[RR * NS];       // cosine matrix           84 MB
__device__ float g_term[RR];          // per-row loss terms

// ---------------------------------------------------------------------------
// Kernel A: per-speaker prep. block = speaker n, thread = dim d (256 threads)
// ---------------------------------------------------------------------------
__global__ void prep_kernel(const float* __restrict__ inp) {
    const int n = blockIdx.x;
    const int d = threadIdx.x;
    const float* base = inp + (size_t)n * MU * DD + d;

    float x[MU];
    float cent = 0.f;
#pragma unroll
    for (int m = 0; m < MU; m++) { x[m] = base[m * DD]; cent += x[m]; }
    cent *= (1.0f / MU);

    __shared__ float red[61][8];
    const int lane = d & 31, warp = d >> 5;

#pragma unroll
    for (int m = 0; m < MU; m++) {
        const float e = (cent * (float)MU - x[m]) * (1.0f / (MU - 1));
        float v0 = x[m] * x[m];
        float v1 = e * e;
        float v2 = x[m] * e;
#pragma unroll
        for (int o = 16; o > 0; o >>= 1) {
            v0 += __shfl_xor_sync(0xffffffffu, v0, o);
            v1 += __shfl_xor_sync(0xffffffffu, v1, o);
            v2 += __shfl_xor_sync(0xffffffffu, v2, o);
        }
        if (lane == 0) { red[m][warp] = v0; red[20 + m][warp] = v1; red[40 + m][warp] = v2; }
    }
    {
        float vc = cent * cent;
#pragma unroll
        for (int o = 16; o > 0; o >>= 1) vc += __shfl_xor_sync(0xffffffffu, vc, o);
        if (lane == 0) red[60][warp] = vc;
    }
    __syncthreads();

    __shared__ float res[61];
    if (d < 61) {
        float s = 0.f;
#pragma unroll
        for (int w = 0; w < 8; w++) s += red[d][w];
        res[d] = s;
    }
    __syncthreads();

    // normalized centroid
    g_chat[n * DD + d] = cent * rsqrtf(res[60]);

    // normalized utterances
#pragma unroll
    for (int m = 0; m < MU; m++) {
        g_uhat[(size_t)(n * MU + m) * DD + d] = x[m] * rsqrtf(res[m]);
    }

    // self cosine: (x . e) / (|x| |e|)
    if (d < MU) {
        g_cself[n * MU + d] = res[40 + d] * rsqrtf(res[d] * res[20 + d]);
    }
}

// ---------------------------------------------------------------------------
// Kernel B: cs = u_hat [RR,DD] @ c_hat^T [DD,NS]   (both K-major)
// 64x64 tile per 256-thread block, 4x4 micro-tile, BK=32
// ---------------------------------------------------------------------------
#define BM 64
#define BN 64
#define BK 32

__global__ void __launch_bounds__(256) gemm_kernel() {
    __shared__ float As[BK][BM + 4];
    __shared__ float Bs[BK][BN + 4];

    const int bx = blockIdx.x;   // col tile (0..15)
    const int by = blockIdx.y;   // row tile (0..319)
    const int tid = threadIdx.x; // 0..255
    const int tx = tid & 15;
    const int ty = tid >> 4;

    const int lr = tid >> 3;          // 0..31 loader row
    const int lc = (tid & 7) << 2;    // 0,4,...,28 loader k offset

    float acc[4][4] = {};

    const float* Aptr = g_uhat + (size_t)(by * BM) * DD;
    const float* Bptr = g_chat + (size_t)(bx * BN) * DD;

    for (int k0 = 0; k0 < DD; k0 += BK) {
#pragma unroll
        for (int i = 0; i < 2; i++) {
            const int row = lr + i * 32;
            float4 va = *(const float4*)&Aptr[(size_t)row * DD + k0 + lc];
            As[lc + 0][row] = va.x; As[lc + 1][row] = va.y;
            As[lc + 2][row] = va.z; As[lc + 3][row] = va.w;
            float4 vb = *(const float4*)&Bptr[(size_t)row * DD + k0 + lc];
            Bs[lc + 0][row] = vb.x; Bs[lc + 1][row] = vb.y;
            Bs[lc + 2][row] = vb.z; Bs[lc + 3][row] = vb.w;
        }
        __syncthreads();

#pragma unroll
        for (int k = 0; k < BK; k++) {
            float4 ra = *(const float4*)&As[k][ty * 4];
            float4 rb = *(const float4*)&Bs[k][tx * 4];
            acc[0][0] += ra.x * rb.x; acc[0][1] += ra.x * rb.y;
            acc[0][2] += ra.x * rb.z; acc[0][3] += ra.x * rb.w;
            acc[1][0] += ra.y * rb.x; acc[1][1] += ra.y * rb.y;
            acc[1][2] += ra.y * rb.z; acc[1][3] += ra.y * rb.w;
            acc[2][0] += ra.z * rb.x; acc[2][1] += ra.z * rb.y;
            acc[2][2] += ra.z * rb.z; acc[2][3] += ra.z * rb.w;
            acc[3][0] += ra.w * rb.x; acc[3][1] += ra.w * rb.y;
            acc[3][2] += ra.w * rb.z; acc[3][3] += ra.w * rb.w;
        }
        __syncthreads();
    }

    const int col0 = bx * BN + tx * 4;
#pragma unroll
    for (int i = 0; i < 4; i++) {
        const int row = by * BM + ty * 4 + i;
        *(float4*)&g_cs[(size_t)row * NS + col0] =
            make_float4(acc[i][0], acc[i][1], acc[i][2], acc[i][3]);
    }
}

// ---------------------------------------------------------------------------
// Kernel C: per-row logsumexp + term.  block = row r (20480), 256 threads
// ---------------------------------------------------------------------------
__global__ void lse_kernel(const float* __restrict__ wp, const float* __restrict__ bp) {
    const int r = blockIdx.x;
    const int n = r / MU;
    const int t = threadIdx.x;
    const float w = *wp, b = *bp;
    const float cself = g_cself[r];

    float v[4];
#pragma unroll
    for (int j = 0; j < 4; j++) {
        const int c = t + j * 256;
        float cs = g_cs[(size_t)r * NS + c];
        if (c == n) cs = cself;
        v[j] = w * cs + b;
    }

    __shared__ float sm[8];
    const int lane = t & 31, warp = t >> 5;

    // block max
    float mx = fmaxf(fmaxf(v[0], v[1]), fmaxf(v[2], v[3]));
#pragma unroll
    for (int o = 16; o > 0; o >>= 1) mx = fmaxf(mx, __shfl_xor_sync(0xffffffffu, mx, o));
    if (lane == 0) sm[warp] = mx;
    __syncthreads();
    mx = sm[0];
#pragma unroll
    for (int wj = 1; wj < 8; wj++) mx = fmaxf(mx, sm[wj]);
    __syncthreads();

    // block sum of exp
    float s = 0.f;
#pragma unroll
    for (int j = 0; j < 4; j++) s += __expf(v[j] - mx) * 0.f + expf(v[j] - mx);
#pragma unroll
    for (int o = 16; o > 0; o >>= 1) s += __shfl_xor_sync(0xffffffffu, s, o);
    if (lane == 0) sm[warp] = s;
    __syncthreads();

    if (t == 0) {
        float tot = 0.f;
#pragma unroll
        for (int wj = 0; wj < 8; wj++) tot += sm[wj];
        const float lse = mx + logf(tot);
        const float sim_self = w * cself + b;
        g_term[r] = lse - sim_self;
    }
}

// ---------------------------------------------------------------------------
// Kernel D: deterministic final reduction
// ---------------------------------------------------------------------------
__global__ void final_kernel(float* __restrict__ out) {
    const int t = threadIdx.x; // 1024
    float s = 0.f;
    for (int i = t; i < RR; i += 1024) s += g_term[i];

    __shared__ float sm[32];
    const int lane = t & 31, warp = t >> 5;
#pragma unroll
    for (int o = 16; o > 0; o >>= 1) s += __shfl_xor_sync(0xffffffffu, s, o);
    if (lane == 0) sm[warp] = s;
    __syncthreads();
    if (t < 32) {
        s = sm[t];
#pragma unroll
        for (int o = 16; o > 0; o >>= 1) s += __shfl_xor_sync(0xffffffffu, s, o);
        if (t == 0) out[0] = s;
    }
}

// ---------------------------------------------------------------------------
extern "C" void kernel_launch(void* const* d_in, const int* in_sizes, int n_in,
                              void* d_out, int out_size) {
    const float* inp = (const float*)d_in[0];
    const float* w   = (const float*)d_in[1];
    const float* b   = (const float*)d_in[2];
    float* out = (float*)d_out;

    prep_kernel<<<NS, 256>>>(inp);

    dim3 grid(NS / BN, RR / BM);
    gemm_kernel<<<grid, 256>>>();

    lse_kernel<<<RR, 256>>>(w, b);

    final_kernel<<<1, 1024>>>(out);
}

// round 3
// speedup vs baseline: 4.4988x; 4.4988x over previous
#include <cuda_runtime.h>
#include <cuda_bf16.h>
#include <math.h>

// Problem constants
#define NS 1024          // speakers
#define MU 20            // utterances per speaker
#define DD 256           // embedding dim
#define RR (NS*MU)       // total rows = 20480

// Scratch (device globals: allocation-free requirement)
__device__ __nv_bfloat16 g_uhat[RR * DD];   // normalized utterances (bf16)  10.5 MB
__device__ __nv_bfloat16 g_chat[NS * DD];   // normalized centroids  (bf16)   0.5 MB
__device__ float g_cself[RR];               // self (leave-one-out) cosine (fp32 exact)
__device__ float g_term[RR];                // per-row loss terms

// ---------------------------------------------------------------------------
// fast exp(v) where the argument is already in log2 domain: computes 2^y.
// y = v*log2(e) is formed by the caller.  Valid for y in ~[-100, 100].
// Taylor-5 of 2^f on [-0.5,0.5]: max rel err ~2.4e-6.
// ---------------------------------------------------------------------------
__device__ __forceinline__ float exp2_fast(float y) {
    const float MAGIC = 12582912.0f;           // 1.5 * 2^23
    float t  = __fadd_rn(y, MAGIC);            // low mantissa bits = rint(y)
    float kf = __fadd_rn(t, -MAGIC);           // rint(y) as float
    float f  = y - kf;                         // in [-0.5, 0.5]
    float p  = 0.00133335581f;                 // ln2^5/120
    p = fmaf(p, f, 0.00961812911f);            // ln2^4/24
    p = fmaf(p, f, 0.05550410866f);            // ln2^3/6
    p = fmaf(p, f, 0.24022650696f);            // ln2^2/2
    p = fmaf(p, f, 0.69314718056f);            // ln2
    p = fmaf(p, f, 1.0f);
    // bits(t) = 0x4B400000 + k ; low 9 bits of 0x4B400000 are 0, so
    // (bits(t) << 23) == (k << 23) mod 2^32  -> splice exponent
    return __int_as_float(__float_as_int(p) + (__float_as_int(t) << 23));
}

// ---------------------------------------------------------------------------
// Kernel A: per-speaker prep. block = speaker n, thread = dim d (256 threads)
// ---------------------------------------------------------------------------
__global__ void prep_kernel(const float* __restrict__ inp) {
    const int n = blockIdx.x;
    const int d = threadIdx.x;
    const float* base = inp + (size_t)n * MU * DD + d;

    float x[MU];
    float cent = 0.f;
#pragma unroll
    for (int m = 0; m < MU; m++) { x[m] = base[m * DD]; cent += x[m]; }
    cent *= (1.0f / MU);

    __shared__ float red[61][8];
    const int lane = d & 31, warp = d >> 5;

#pragma unroll
    for (int m = 0; m < MU; m++) {
        const float e = (cent * (float)MU - x[m]) * (1.0f / (MU - 1));
        float v0 = x[m] * x[m];
        float v1 = e * e;
        float v2 = x[m] * e;
#pragma unroll
        for (int o = 16; o > 0; o >>= 1) {
            v0 += __shfl_xor_sync(0xffffffffu, v0, o);
            v1 += __shfl_xor_sync(0xffffffffu, v1, o);
            v2 += __shfl_xor_sync(0xffffffffu, v2, o);
        }
        if (lane == 0) { red[m][warp] = v0; red[20 + m][warp] = v1; red[40 + m][warp] = v2; }
    }
    {
        float vc = cent * cent;
#pragma unroll
        for (int o = 16; o > 0; o >>= 1) vc += __shfl_xor_sync(0xffffffffu, vc, o);
        if (lane == 0) red[60][warp] = vc;
    }
    __syncthreads();

    __shared__ float res[61];
    if (d < 61) {
        float s = 0.f;
#pragma unroll
        for (int w = 0; w < 8; w++) s += red[d][w];
        res[d] = s;
    }
    __syncthreads();

    // normalized centroid -> bf16
    g_chat[n * DD + d] = __float2bfloat16(cent * rsqrtf(res[60]));

    // normalized utterances -> bf16
#pragma unroll
    for (int m = 0; m < MU; m++) {
        g_uhat[(size_t)(n * MU + m) * DD + d] = __float2bfloat16(x[m] * rsqrtf(res[m]));
    }

    // self cosine: (x . e) / (|x| |e|)   (kept fp32 exact)
    if (d < MU) {
        g_cself[n * MU + d] = res[40 + d] * rsqrtf(res[d] * res[20 + d]);
    }
}

// ---------------------------------------------------------------------------
// Kernel B: fused  cs = u_hat @ c_hat^T  + scaled-softmax-denominator.
// 320 blocks x 128 threads (4 warps). Block owns 64 rows. Warp owns 16 rows.
// A tile (64x256 bf16) pre-loaded into register fragments once.
// Loop 16 chunks of 64 columns through smem; m16n8k16 bf16 HMMA;
// epilogue accumulates sum of exp(w*cs+b) per row (no max pass needed:
// sim in [-15.6, 5.6] can't overflow fp32).
// ---------------------------------------------------------------------------
__global__ void __launch_bounds__(128) fused_kernel(const float* __restrict__ wp,
                                                    const float* __restrict__ bp) {
    __shared__ __align__(16) unsigned char smemA[64 * 512];  // 32 KB bf16, swizzled
    __shared__ __align__(16) unsigned char smemB[64 * 512];  // 32 KB bf16, swizzled

    const int tid  = threadIdx.x;
    const int warp = tid >> 5;
    const int lane = tid & 31;
    const int r0   = blockIdx.x * 64;

    const float w  = *wp;
    const float bb = *bp;
    const float L2E = 1.4426950408889634f;
    const float wl = w * L2E, bl = bb * L2E;   // log2-domain scale

    // ---- load A tile (rows r0..r0+63, all 256 k) with XOR-16B swizzle ----
    {
        const uint4* src = (const uint4*)(g_uhat + (size_t)r0 * DD);
        for (int i = tid; i < 64 * 32; i += 128) {
            const int row = i >> 5, c = i & 31;
            uint4 v = src[row * 32 + c];
            *(uint4*)(smemA + row * 512 + ((c ^ (row & 7)) << 4)) = v;
        }
    }
    __syncthreads();

    // ---- preload A fragments: 16 k-steps x ldmatrix.x4 (64 regs/thread) ----
    unsigned aFrag[16][4];
    {
        const unsigned baseA = (unsigned)__cvta_generic_to_shared(smemA);
        const int rr = warp * 16 + (lane & 15);
        const unsigned rowA = baseA + rr * 512;
        const int x7 = rr & 7;
        const int hi = lane >> 4;
#pragma unroll
        for (int ks = 0; ks < 16; ks++) {
            const unsigned addr = rowA + (((ks * 2 + hi) ^ x7) << 4);
            asm volatile("ldmatrix.sync.aligned.m8n8.x4.shared.b16 {%0,%1,%2,%3}, [%4];"
                         : "=r"(aFrag[ks][0]), "=r"(aFrag[ks][1]),
                           "=r"(aFrag[ks][2]), "=r"(aFrag[ks][3])
                         : "r"(addr));
        }
    }

    // ---- per-thread row metadata for the epilogue ----
    const int q     = lane & 3;                  // column quad
    const int gr0   = r0 + warp * 16 + (lane >> 2);   // rows t/4 and t/4+8
    const int gr1   = gr0 + 8;
    const int spk0  = gr0 / MU, spk1 = gr1 / MU;
    const float cs0 = g_cself[gr0], cs1 = g_cself[gr1];
    const float ys0 = fmaf(cs0, wl, bl);         // diag value, log2 domain
    const float ys1 = fmaf(cs1, wl, bl);
    float S0 = 0.f, S1 = 0.f;

    const unsigned baseB = (unsigned)__cvta_generic_to_shared(smemB);
    const int nn = lane & 15;
    const int hi = lane >> 4;

    for (int chk = 0; chk < 16; chk++) {
        const int c0 = chk * 64;
        // load B chunk (cols c0..c0+63, all 256 k)
        {
            const uint4* srcB = (const uint4*)(g_chat + (size_t)c0 * DD);
            for (int i = tid; i < 64 * 32; i += 128) {
                const int row = i >> 5, c = i & 31;
                uint4 v = srcB[row * 32 + c];
                *(uint4*)(smemB + row * 512 + ((c ^ (row & 7)) << 4)) = v;
            }
        }
        __syncthreads();

        float acc[8][4];
#pragma unroll
        for (int j = 0; j < 8; j++)
#pragma unroll
            for (int p = 0; p < 4; p++) acc[j][p] = 0.f;

#pragma unroll
        for (int ks = 0; ks < 16; ks++) {
            unsigned bfr[4][4];
#pragma unroll
            for (int ntp = 0; ntp < 4; ntp++) {
                const int rrn = ntp * 16 + nn;
                const unsigned addr = baseB + rrn * 512 +
                                      (((ks * 2 + hi) ^ (rrn & 7)) << 4);
                asm volatile("ldmatrix.sync.aligned.m8n8.x4.shared.b16 {%0,%1,%2,%3}, [%4];"
                             : "=r"(bfr[ntp][0]), "=r"(bfr[ntp][1]),
                               "=r"(bfr[ntp][2]), "=r"(bfr[ntp][3])
                             : "r"(addr));
            }
#pragma unroll
            for (int ntp = 0; ntp < 4; ntp++) {
                asm volatile(
                    "mma.sync.aligned.m16n8k16.row.col.f32.bf16.bf16.f32 "
                    "{%0,%1,%2,%3}, {%4,%5,%6,%7}, {%8,%9}, {%0,%1,%2,%3};"
                    : "+f"(acc[2 * ntp][0]), "+f"(acc[2 * ntp][1]),
                      "+f"(acc[2 * ntp][2]), "+f"(acc[2 * ntp][3])
                    : "r"(aFrag[ks][0]), "r"(aFrag[ks][1]),
                      "r"(aFrag[ks][2]), "r"(aFrag[ks][3]),
                      "r"(bfr[ntp][0]), "r"(bfr[ntp][2]));
                asm volatile(
                    "mma.sync.aligned.m16n8k16.row.col.f32.bf16.bf16.f32 "
                    "{%0,%1,%2,%3}, {%4,%5,%6,%7}, {%8,%9}, {%0,%1,%2,%3};"
                    : "+f"(acc[2 * ntp + 1][0]), "+f"(acc[2 * ntp + 1][1]),
                      "+f"(acc[2 * ntp + 1][2]), "+f"(acc[2 * ntp + 1][3])
                    : "r"(aFrag[ks][0]), "r"(aFrag[ks][1]),
                      "r"(aFrag[ks][2]), "r"(aFrag[ks][3]),
                      "r"(bfr[ntp][1]), "r"(bfr[ntp][3]));
            }
        }
        __syncthreads();   // before next chunk overwrites smemB

        // ---- epilogue: accumulate exp(sim) for this 64-col chunk ----
#pragma unroll
        for (int j = 0; j < 8; j++) {
            const int gcb = c0 + j * 8 + 2 * q;
#pragma unroll
            for (int p = 0; p < 4; p++) {
                const int gc = gcb + (p & 1);
                float y = fmaf(acc[j][p], wl, bl);
                if (p < 2) {
                    if (gc == spk0) y = ys0;
                    S0 += exp2_fast(y);
                } else {
                    if (gc == spk1) y = ys1;
                    S1 += exp2_fast(y);
                }
            }
        }
    }

    // reduce the 64-col partial sums across the 4 quad lanes (fixed order)
    S0 += __shfl_xor_sync(0xffffffffu, S0, 1);
    S0 += __shfl_xor_sync(0xffffffffu, S0, 2);
    S1 += __shfl_xor_sync(0xffffffffu, S1, 1);
    S1 += __shfl_xor_sync(0xffffffffu, S1, 2);

    if (q == 0) {
        g_term[gr0] = logf(S0) - fmaf(cs0, w, bb);
        g_term[gr1] = logf(S1) - fmaf(cs1, w, bb);
    }
}

// ---------------------------------------------------------------------------
// Kernel C: deterministic final reduction (vectorized)
// ---------------------------------------------------------------------------
__global__ void final_kernel(float* __restrict__ out) {
    const int t = threadIdx.x; // 1024
    const float4* src = (const float4*)g_term;
    float s = 0.f;
#pragma unroll
    for (int i = 0; i < RR / 4 / 1024; i++) {
        float4 v = src[t + i * 1024];
        s += (v.x + v.y) + (v.z + v.w);
    }

    __shared__ float sm[32];
    const int lane = t & 31, warp = t >> 5;
#pragma unroll
    for (int o = 16; o > 0; o >>= 1) s += __shfl_xor_sync(0xffffffffu, s, o);
    if (lane == 0) sm[warp] = s;
    __syncthreads();
    if (t < 32) {
        s = sm[t];
#pragma unroll
        for (int o = 16; o > 0; o >>= 1) s += __shfl_xor_sync(0xffffffffu, s, o);
        if (t == 0) out[0] = s;
    }
}

// ---------------------------------------------------------------------------
extern "C" void kernel_launch(void* const* d_in, const int* in_sizes, int n_in,
                              void* d_out, int out_size) {
    const float* inp = (const float*)d_in[0];
    const float* w   = (const float*)d_in[1];
    const float* b   = (const float*)d_in[2];
    float* out = (float*)d_out;

    prep_kernel<<<NS, 256>>>(inp);
    fused_kernel<<<RR / 64, 128>>>(w, b);
    final_kernel<<<1, 1024>>>(out);
}

// round 5
// speedup vs baseline: 6.2739x; 1.3946x over previous
#include <cuda_runtime.h>
#include <cuda_bf16.h>
#include <math.h>
#include <stdint.h>

// Problem constants
#define NS 1024          // speakers
#define MU 20            // utterances per speaker
#define DD 256           // embedding dim
#define RR (NS*MU)       // total rows = 20480

// Scratch (device globals: allocation-free requirement)
__device__ __nv_bfloat16 g_uhat[RR * DD];   // normalized utterances (bf16)
__device__ __nv_bfloat16 g_chat[NS * DD];   // normalized centroids  (bf16)
__device__ float g_cself[RR];               // leave-one-out cosine (fp32 exact)
__device__ float g_partial[RR * 4];         // per-(row, col-chunk) exp sums
__device__ float g_blocksum[160];           // stage-1 reduction results

// ---------------------------------------------------------------------------
// fast 2^y (y in ~[-100,100]); poly rel err ~2.4e-6, all FMA-pipe.
// ---------------------------------------------------------------------------
__device__ __forceinline__ float exp2_fast(float y) {
    const float MAGIC = 12582912.0f;           // 1.5 * 2^23
    float t  = __fadd_rn(y, MAGIC);
    float kf = __fadd_rn(t, -MAGIC);
    float f  = y - kf;                         // [-0.5, 0.5]
    float p  = 0.00133335581f;
    p = fmaf(p, f, 0.00961812911f);
    p = fmaf(p, f, 0.05550410866f);
    p = fmaf(p, f, 0.24022650696f);
    p = fmaf(p, f, 0.69314718056f);
    p = fmaf(p, f, 1.0f);
    return __int_as_float(__float_as_int(p) + (__float_as_int(t) << 23));
}

__device__ __forceinline__ float warp_sum(float v) {
#pragma unroll
    for (int o = 16; o > 0; o >>= 1) v += __shfl_xor_sync(0xffffffffu, v, o);
    return v;
}

// ---------------------------------------------------------------------------
// Kernel A: prep. 4 speakers/block, 64 threads/speaker, float4/thread, x in regs.
// Gram scalars: a_m=||x_m||^2, b_m=x_m.S, c=||S||^2, S=sum_m x_m.
//   chat  = S * rsqrt(c)                      (mean scale cancels)
//   uhat  = x * rsqrt(a)
//   cself = (b-a) * rsqrt(a*(a-2b+c))         ((M-1) cancels)
// ---------------------------------------------------------------------------
__global__ void __launch_bounds__(256) prep_kernel(const float* __restrict__ inp) {
    const int sub = threadIdx.x >> 6;      // speaker within block
    const int t   = threadIdx.x & 63;
    const int spk = blockIdx.x * 4 + sub;
    const int lane = t & 31, w2 = t >> 5;

    const float4* base = (const float4*)(inp + (size_t)spk * MU * DD) + t;

    float4 x[MU];
    float4 S = make_float4(0.f, 0.f, 0.f, 0.f);
#pragma unroll
    for (int m = 0; m < MU; m++) {
        x[m] = base[m * 64];
        S.x += x[m].x; S.y += x[m].y; S.z += x[m].z; S.w += x[m].w;
    }

    __shared__ float sa[4][2][MU], sb[4][2][MU], sc[4][2];

    {
        float cp = warp_sum(S.x * S.x + S.y * S.y + S.z * S.z + S.w * S.w);
        if (lane == 0) sc[sub][w2] = cp;
    }
#pragma unroll
    for (int m = 0; m < MU; m++) {
        float a = x[m].x * x[m].x + x[m].y * x[m].y + x[m].z * x[m].z + x[m].w * x[m].w;
        float b = x[m].x * S.x + x[m].y * S.y + x[m].z * S.z + x[m].w * S.w;
        a = warp_sum(a); b = warp_sum(b);
        if (lane == 0) { sa[sub][w2][m] = a; sb[sub][w2][m] = b; }
    }
    __syncthreads();

    const float c = sc[sub][0] + sc[sub][1];

    // chat
    {
        const float rc = rsqrtf(c);
        __nv_bfloat162 p0 = __floats2bfloat162_rn(S.x * rc, S.y * rc);
        __nv_bfloat162 p1 = __floats2bfloat162_rn(S.z * rc, S.w * rc);
        uint2 v = make_uint2(*(uint32_t*)&p0, *(uint32_t*)&p1);
        ((uint2*)g_chat)[spk * 64 + t] = v;
    }
    // uhat
#pragma unroll
    for (int m = 0; m < MU; m++) {
        const float a = sa[sub][0][m] + sa[sub][1][m];
        const float ra = rsqrtf(a);
        __nv_bfloat162 p0 = __floats2bfloat162_rn(x[m].x * ra, x[m].y * ra);
        __nv_bfloat162 p1 = __floats2bfloat162_rn(x[m].z * ra, x[m].w * ra);
        uint2 v = make_uint2(*(uint32_t*)&p0, *(uint32_t*)&p1);
        ((uint2*)g_uhat)[(size_t)(spk * MU + m) * 64 + t] = v;
    }
    // cself
    if (t < MU) {
        const float a = sa[sub][0][t] + sa[sub][1][t];
        const float b = sb[sub][0][t] + sb[sub][1][t];
        g_cself[spk * MU + t] = (b - a) * rsqrtf(a * (a - 2.f * b + c));
    }
}

// ---------------------------------------------------------------------------
// Kernel B: fused GEMM + exp-sum.  mma.sync m16n8k16 bf16 (HMMA path).
// Block: 128 threads (4 warps), tile M=128 x N=256, K=256.
// grid = 160 row-tiles x 4 col-chunks = 640 blocks, 2 CTAs/SM.
// A (128x256 bf16, 64KB) cp.async'ed once, preloaded to frags (warp_M=32 ->
// halved LDSM traffic). B streamed in 8 chunks of 32 cols, double-buffered
// cp.async. Epilogue per chunk: exp2(wl*cs+bl) accumulated per row in regs.
// ---------------------------------------------------------------------------
#define A_BYTES  65536                // 128 rows * 512B
#define BCH_BYTES 16384               // 32 rows * 512B
#define FUSED_SMEM (1024 + A_BYTES + 2*BCH_BYTES)   // 99328

__device__ __forceinline__ void cp_async16(uint32_t dst, const void* src) {
    asm volatile("cp.async.cg.shared.global [%0], [%1], 16;" :: "r"(dst), "l"(src));
}
__device__ __forceinline__ uint32_t smem_u32(const void* p) {
    return (uint32_t)__cvta_generic_to_shared(p);
}
__device__ __forceinline__ void ldsm_x4(unsigned* r, uint32_t addr) {
    asm volatile("ldmatrix.sync.aligned.m8n8.x4.shared.b16 {%0,%1,%2,%3}, [%4];"
                 : "=r"(r[0]), "=r"(r[1]), "=r"(r[2]), "=r"(r[3]) : "r"(addr));
}
__device__ __forceinline__ void mma16816(float* c, const unsigned* a,
                                         unsigned b0, unsigned b1) {
    asm volatile(
        "mma.sync.aligned.m16n8k16.row.col.f32.bf16.bf16.f32 "
        "{%0,%1,%2,%3}, {%4,%5,%6,%7}, {%8,%9}, {%0,%1,%2,%3};"
        : "+f"(c[0]), "+f"(c[1]), "+f"(c[2]), "+f"(c[3])
        : "r"(a[0]), "r"(a[1]), "r"(a[2]), "r"(a[3]), "r"(b0), "r"(b1));
}

__global__ void __launch_bounds__(128) fused_kernel(const float* __restrict__ wp,
                                                    const float* __restrict__ bp) {
    extern __shared__ __align__(16) char smem[];
    const uint32_t sbase = smem_u32(smem);
    const uint32_t sA  = (sbase + 1023u) & ~1023u;
    const uint32_t sB0 = sA + A_BYTES;
    const uint32_t sB1 = sB0 + BCH_BYTES;

    const int tid  = threadIdx.x;
    const int wid  = tid >> 5;
    const int lane = tid & 31;
    const int row_tile = blockIdx.x >> 2;
    const int cc       = blockIdx.x & 3;
    const int r0 = row_tile * 128;
    const int c0 = cc * 256;

    const __nv_bfloat16* Ag = g_uhat + (size_t)r0 * DD;
    const __nv_bfloat16* Bg = g_chat + (size_t)c0 * DD;

    // ---- prologue: A (group 0), B chunk 0 (group 1), B chunk 1 (group 2) ----
#pragma unroll
    for (int j = 0; j < 32; j++) {
        const int i = tid + j * 128;
        const int r = i >> 5, c = i & 31;
        cp_async16(sA + r * 512 + ((c ^ (r & 7)) << 4), Ag + (size_t)r * DD + c * 8);
    }
    asm volatile("cp.async.commit_group;");
#pragma unroll
    for (int j = 0; j < 8; j++) {
        const int i = tid + j * 128;
        const int r = i >> 5, c = i & 31;
        cp_async16(sB0 + r * 512 + ((c ^ (r & 7)) << 4), Bg + (size_t)r * DD + c * 8);
    }
    asm volatile("cp.async.commit_group;");
#pragma unroll
    for (int j = 0; j < 8; j++) {
        const int i = tid + j * 128;
        const int r = i >> 5, c = i & 31;
        cp_async16(sB1 + r * 512 + ((c ^ (r & 7)) << 4),
                   Bg + (size_t)(32 + r) * DD + c * 8);
    }
    asm volatile("cp.async.commit_group;");

    asm volatile("cp.async.wait_group 1;");   // A + B0 complete
    __syncthreads();

    // ---- preload A fragments: warp rows wid*32..+31, 16 ksteps x 2 m-tiles ----
    unsigned aF[16][2][4];
    const int hi = lane >> 4;
#pragma unroll
    for (int ks = 0; ks < 16; ks++) {
#pragma unroll
        for (int mi = 0; mi < 2; mi++) {
            const int rr = wid * 32 + mi * 16 + (lane & 15);
            ldsm_x4(aF[ks][mi], sA + rr * 512 + (((ks * 2 + hi) ^ (rr & 7)) << 4));
        }
    }

    // ---- per-thread row metadata (4 output rows per thread) ----
    const float w  = *wp;
    const float bb = *bp;
    const float L2E = 1.4426950408889634f;
    const float wl = w * L2E, bl = bb * L2E;

    float S[4];
    int   spkv[4];
    float ysv[4];
#pragma unroll
    for (int si = 0; si < 4; si++) {
        const int row = r0 + wid * 32 + (si >> 1) * 16 + (si & 1) * 8 + (lane >> 2);
        spkv[si] = row / MU;
        ysv[si]  = fmaf(g_cself[row], wl, bl);
        S[si] = 0.f;
    }
    const int q2 = 2 * (lane & 3);

    // ---- main loop over 8 B chunks of 32 cols ----
#pragma unroll 1
    for (int ch = 0; ch < 8; ch++) {
        const uint32_t bBuf = (ch & 1) ? sB1 : sB0;

        float acc[2][4][4];
#pragma unroll
        for (int mi = 0; mi < 2; mi++)
#pragma unroll
            for (int nt = 0; nt < 4; nt++)
#pragma unroll
                for (int p = 0; p < 4; p++) acc[mi][nt][p] = 0.f;

#pragma unroll
        for (int ks = 0; ks < 16; ks++) {
            unsigned bf[2][4];
#pragma unroll
            for (int ntp = 0; ntp < 2; ntp++) {
                const int rrn = ntp * 16 + (lane & 15);
                ldsm_x4(bf[ntp],
                        bBuf + rrn * 512 + (((ks * 2 + hi) ^ (rrn & 7)) << 4));
            }
#pragma unroll
            for (int mi = 0; mi < 2; mi++) {
#pragma unroll
                for (int nt = 0; nt < 4; nt++) {
                    const int ntp = nt >> 1, pr = nt & 1;
                    mma16816(acc[mi][nt], aF[ks][mi], bf[ntp][pr], bf[ntp][pr + 2]);
                }
            }
        }

        // epilogue: exp-accumulate this chunk's 32 values into S
        const int colb = c0 + ch * 32;
#pragma unroll
        for (int mi = 0; mi < 2; mi++) {
#pragma unroll
            for (int nt = 0; nt < 4; nt++) {
#pragma unroll
                for (int p = 0; p < 4; p++) {
                    const int col = colb + nt * 8 + q2 + (p & 1);
                    const int si = mi * 2 + (p >> 1);
                    float y = fmaf(acc[mi][nt][p], wl, bl);
                    if (col == spkv[si]) y = ysv[si];
                    S[si] += exp2_fast(y);
                }
            }
        }

        __syncthreads();                       // done reading bBuf
        if (ch + 2 < 8) {                      // refill it with chunk ch+2
            const __nv_bfloat16* Bsrc = Bg + (size_t)(ch + 2) * 32 * DD;
#pragma unroll
            for (int j = 0; j < 8; j++) {
                const int i = tid + j * 128;
                const int r = i >> 5, c = i & 31;
                cp_async16(bBuf + r * 512 + ((c ^ (r & 7)) << 4),
                           Bsrc + (size_t)r * DD + c * 8);
            }
            asm volatile("cp.async.commit_group;");
            asm volatile("cp.async.wait_group 1;");   // chunk ch+1 ready
        } else {
            asm volatile("cp.async.wait_group 0;");
        }
        __syncthreads();
    }

    // ---- reduce partial exp-sums across the 4 quad lanes (fixed order) ----
#pragma unroll
    for (int si = 0; si < 4; si++) {
        S[si] += __shfl_xor_sync(0xffffffffu, S[si], 1);
        S[si] += __shfl_xor_sync(0xffffffffu, S[si], 2);
    }
    if ((lane & 3) == 0) {
#pragma unroll
        for (int si = 0; si < 4; si++) {
            const int row = r0 + wid * 32 + (si >> 1) * 16 + (si & 1) * 8 + (lane >> 2);
            g_partial[row * 4 + cc] = S[si];
        }
    }
}

// ---------------------------------------------------------------------------
// Kernel C1: per-row finalize + per-block deterministic reduction (160 blocks)
// ---------------------------------------------------------------------------
__global__ void __launch_bounds__(128) final1_kernel(const float* __restrict__ wp,
                                                     const float* __restrict__ bp) {
    const int r = blockIdx.x * 128 + threadIdx.x;
    const float w = *wp, bb = *bp;
    float4 p = ((const float4*)g_partial)[r];
    const float Ssum = (p.x + p.y) + (p.z + p.w);
    float s = __logf(Ssum) - fmaf(g_cself[r], w, bb);

    __shared__ float sm[4];
    const int lane = threadIdx.x & 31, warp = threadIdx.x >> 5;
    s = warp_sum(s);
    if (lane == 0) sm[warp] = s;
    __syncthreads();
    if (threadIdx.x == 0)
        g_blocksum[blockIdx.x] = (sm[0] + sm[1]) + (sm[2] + sm[3]);
}

// ---------------------------------------------------------------------------
// Kernel C2: final deterministic reduction (1 warp)
// ---------------------------------------------------------------------------
__global__ void final2_kernel(float* __restrict__ out) {
    const int t = threadIdx.x;  // 32
    float s = 0.f;
#pragma unroll
    for (int i = 0; i < 5; i++) s += g_blocksum[t + i * 32];
    s = warp_sum(s);
    if (t == 0) out[0] = s;
}

// ---------------------------------------------------------------------------
extern "C" void kernel_launch(void* const* d_in, const int* in_sizes, int n_in,
                              void* d_out, int out_size) {
    const float* inp = (const float*)d_in[0];
    const float* w   = (const float*)d_in[1];
    const float* b   = (const float*)d_in[2];
    float* out = (float*)d_out;

    cudaFuncSetAttribute(fused_kernel, cudaFuncAttributeMaxDynamicSharedMemorySize,
                         FUSED_SMEM);

    prep_kernel<<<NS / 4, 256>>>(inp);
    fused_kernel<<<640, 128, FUSED_SMEM>>>(w, b);
    final1_kernel<<<160, 128>>>(w, b);
    final2_kernel<<<1, 32>>>(out);
}